// round 2
// baseline (speedup 1.0000x reference)
#include <cuda_runtime.h>
#include <cstdint>

#define Tn 2048
#define Hn 256
#define Bn 256
#define Pn 24

typedef unsigned long long ull;

// Shared memory layout (in floats)
//  Wt  : [160][256]  transposed W_hh rows k in [96,256)          = 40960 floats (160 KB)
//  hsd : [256] float4 {h_b0,h_b0,h_b1,h_b1} duplicated pairs     =  1024 floats (4 KB)
//  red : [8][256] k-slot partials, rows (kslot*2 + b)            =  2048 floats (8 KB)
//  xs  : [2][2048] cached x rows for the CTA's two batches       =  4096 floats (16 KB)
#define OFF_W   0
#define OFF_H   40960
#define OFF_RED 41984
#define OFF_X   44032
#define SMEM_FLOATS 48128
#define SMEM_BYTES (SMEM_FLOATS * 4)

__device__ __forceinline__ void ffma2(ull& a, ull b, ull c) {
    asm("fma.rn.f32x2 %0, %1, %2, %0;" : "+l"(a) : "l"(b), "l"(c));
}
__device__ __forceinline__ ull packf2(float lo, float hi) {
    ull r; asm("mov.b64 %0, {%1, %2};" : "=l"(r) : "f"(lo), "f"(hi)); return r;
}
__device__ __forceinline__ float2 u2f(ull v) {
    float2 r; asm("mov.b64 {%0, %1}, %2;" : "=f"(r.x), "=f"(r.y) : "l"(v)); return r;
}
// tanh(x) = 1 - 2/(e^{2x}+1); ex2+rcp approx, abs err ~4e-7, saturates correctly.
__device__ __forceinline__ float tanh_fast(float v) {
    float e = __expf(2.0f * v);
    return 1.0f - __fdividef(2.0f, e + 1.0f);
}

__global__ void __launch_bounds__(256, 1)
rnn_persistent_kernel(const float* __restrict__ x,
                      const float* __restrict__ W_ih,
                      const float* __restrict__ W_hh,
                      const float* __restrict__ b_ih,
                      const float* __restrict__ b_hh,
                      const float* __restrict__ W_out,
                      const float* __restrict__ b_out,
                      float* __restrict__ out)
{
    extern __shared__ float sm[];
    float*  Wt  = sm + OFF_W;
    float4* hsd = (float4*)(sm + OFF_H);
    float*  red = sm + OFF_RED;
    float*  xs  = sm + OFF_X;

    const int tid   = threadIdx.x;
    const int lane  = tid & 31;
    const int wid   = tid >> 5;
    const int jhalf = wid & 1;        // which half of j-rows this warp covers
    const int kslot = wid >> 1;       // which k residue (mod 4) this warp covers
    const int j0    = jhalf * 128 + lane * 4;
    const int b0    = blockIdx.x * 2;

    // ---------------- init ----------------
    // cache x rows for both batches (coalesced)
    for (int i = tid; i < Tn; i += 256) {
        xs[i]      = x[(size_t)b0 * Tn + i];
        xs[Tn + i] = x[(size_t)(b0 + 1) * Tn + i];
    }
    // smem W: k in [96,256), stored transposed Wt[k-96][j].
    // Read coalesced over k, write strided (one-time cost, conflicts OK).
    for (int idx = tid; idx < 256 * 40; idx += 256) {
        int j  = idx / 40;
        int kc = idx % 40;
        int k0 = 96 + kc * 4;
        float4 w4 = *(const float4*)&W_hh[j * Hn + k0];
        Wt[(k0 - 96 + 0) * 256 + j] = w4.x;
        Wt[(k0 - 96 + 1) * 256 + j] = w4.y;
        Wt[(k0 - 96 + 2) * 256 + j] = w4.z;
        Wt[(k0 - 96 + 3) * 256 + j] = w4.w;
    }
    // register W: k in [0,96), k = it*4 + kslot; packed as j-pairs for f32x2
    ull wr0[24], wr1[24];
    #pragma unroll
    for (int it = 0; it < 24; ++it) {
        int k = it * 4 + kslot;
        float a = W_hh[(j0 + 0) * Hn + k];
        float b = W_hh[(j0 + 1) * Hn + k];
        float c = W_hh[(j0 + 2) * Hn + k];
        float d = W_hh[(j0 + 3) * Hn + k];
        wr0[it] = packf2(a, b);
        wr1[it] = packf2(c, d);
    }
    // per-thread finalize coefficients for j = tid
    const float c1 = W_ih[tid];
    const float c0 = b_ih[tid] + b_hh[tid];
    // h = 0
    hsd[tid] = make_float4(0.f, 0.f, 0.f, 0.f);
    __syncthreads();

    // ---------------- recurrence ----------------
    for (int t = 0; t < Tn; ++t) {
        ull a00 = 0, a01 = 0, a10 = 0, a11 = 0;  // a{jpair}{batch}

        // register-W part: k = it*4 + kslot, it in [0,24)
        const float4* hp = &hsd[kslot];
        #pragma unroll
        for (int it = 0; it < 24; ++it) {
            ulonglong2 hv = *(const ulonglong2*)(hp + it * 4);  // broadcast LDS.128
            ffma2(a00, wr0[it], hv.x);
            ffma2(a01, wr0[it], hv.y);
            ffma2(a10, wr1[it], hv.x);
            ffma2(a11, wr1[it], hv.y);
        }
        // smem-W part: k = it*4 + kslot, it in [24,64); row = k - 96
        const float* wp = &Wt[kslot * 256 + j0];
        const float4* hp2 = &hsd[96 + kslot];
        #pragma unroll 8
        for (int it = 0; it < 40; ++it) {
            ulonglong2 wv = *(const ulonglong2*)(wp + it * 1024);  // contiguous LDS.128
            ulonglong2 hv = *(const ulonglong2*)(hp2 + it * 4);    // broadcast LDS.128
            ffma2(a00, wv.x, hv.x);
            ffma2(a01, wv.x, hv.y);
            ffma2(a10, wv.y, hv.x);
            ffma2(a11, wv.y, hv.y);
        }

        // write k-slot partials: red[(kslot*2 + b)*256 + j0 .. +3]
        {
            float2 p00 = u2f(a00), p10 = u2f(a10);
            float2 p01 = u2f(a01), p11 = u2f(a11);
            *(float4*)&red[(kslot * 2 + 0) * 256 + j0] = make_float4(p00.x, p00.y, p10.x, p10.y);
            *(float4*)&red[(kslot * 2 + 1) * 256 + j0] = make_float4(p01.x, p01.y, p11.x, p11.y);
        }
        __syncthreads();

        // finalize j = tid for both batches
        {
            float s0 = (red[0 * 256 + tid] + red[2 * 256 + tid])
                     + (red[4 * 256 + tid] + red[6 * 256 + tid]);
            float s1 = (red[1 * 256 + tid] + red[3 * 256 + tid])
                     + (red[5 * 256 + tid] + red[7 * 256 + tid]);
            float xv0 = xs[t];
            float xv1 = xs[Tn + t];
            float h0 = tanh_fast(fmaf(xv0, c1, c0) + s0);
            float h1 = tanh_fast(fmaf(xv1, c1, c0) + s1);
            hsd[tid] = make_float4(h0, h0, h1, h1);
        }
        __syncthreads();
    }

    // ---------------- output head: out[b][p] = hT[b] . W_out[p] + b_out[p] ----------------
    if (tid < 2 * Pn) {
        int b = tid / Pn;
        int p = tid % Pn;
        float s = b_out[p];
        const float* wrow = &W_out[p * Hn];
        #pragma unroll 8
        for (int h = 0; h < Hn; ++h) {
            float4 hv = hsd[h];
            float hb = b ? hv.z : hv.x;
            s = fmaf(hb, wrow[h], s);
        }
        out[(size_t)(b0 + b) * Pn + p] = s;
    }
}

extern "C" void kernel_launch(void* const* d_in, const int* in_sizes, int n_in,
                              void* d_out, int out_size) {
    const float* x     = (const float*)d_in[0];
    const float* W_ih  = (const float*)d_in[1];
    const float* W_hh  = (const float*)d_in[2];
    const float* b_ih  = (const float*)d_in[3];
    const float* b_hh  = (const float*)d_in[4];
    const float* W_out = (const float*)d_in[5];
    const float* b_out = (const float*)d_in[6];
    float* out = (float*)d_out;

    cudaFuncSetAttribute(rnn_persistent_kernel,
                         cudaFuncAttributeMaxDynamicSharedMemorySize, SMEM_BYTES);
    rnn_persistent_kernel<<<Bn / 2, 256, SMEM_BYTES>>>(
        x, W_ih, W_hh, b_ih, b_hh, W_out, b_out, out);
}

// round 3
// speedup vs baseline: 1.2384x; 1.2384x over previous
#include <cuda_runtime.h>
#include <cstdint>

#define Tn 2048
#define Hn 256
#define Bn 256
#define Pn 24

#define NT     512        // 16 warps: 8 k-slots x 2 j-halves
#define KSLOTS 8
#define ITS_REG 20        // k-rows [0,160) in registers (40 ull = 80 regs/thread)
#define KREG   (ITS_REG * KSLOTS)          // 160
#define ITS_SM ((Hn - KREG) / KSLOTS)      // 12 -> rows [160,256) in smem (96 KB)

typedef unsigned long long ull;

// Shared memory layout (float offsets)
//  Wt  : [96][256] transposed W_hh rows k in [160,256)  = 24576 floats (96 KB)
//  hsd : [256] float4 {h_b0,h_b0,h_b1,h_b1}             =  1024 floats ( 4 KB)
//  red : [16][256] (kslot*2 + b) partials               =  4096 floats (16 KB)
//  xs  : [2][2048] cached x rows                        =  4096 floats (16 KB)
#define OFF_W   0
#define OFF_H   24576
#define OFF_RED 25600
#define OFF_X   29696
#define SMEM_FLOATS 33792
#define SMEM_BYTES (SMEM_FLOATS * 4)

__device__ __forceinline__ void ffma2(ull& a, ull b, ull c) {
    asm("fma.rn.f32x2 %0, %1, %2, %0;" : "+l"(a) : "l"(b), "l"(c));
}
__device__ __forceinline__ ull packf2(float lo, float hi) {
    ull r; asm("mov.b64 %0, {%1, %2};" : "=l"(r) : "f"(lo), "f"(hi)); return r;
}
__device__ __forceinline__ float2 u2f(ull v) {
    float2 r; asm("mov.b64 {%0, %1}, %2;" : "=f"(r.x), "=f"(r.y) : "l"(v)); return r;
}
// tanh(x) = 1 - 2/(e^{2x}+1); ex2+rcp approx, abs err ~4e-7, saturates correctly.
__device__ __forceinline__ float tanh_fast(float v) {
    float e = __expf(2.0f * v);
    return 1.0f - __fdividef(2.0f, e + 1.0f);
}

__global__ void __launch_bounds__(NT, 1)
rnn_persistent_kernel(const float* __restrict__ x,
                      const float* __restrict__ W_ih,
                      const float* __restrict__ W_hh,
                      const float* __restrict__ b_ih,
                      const float* __restrict__ b_hh,
                      const float* __restrict__ W_out,
                      const float* __restrict__ b_out,
                      float* __restrict__ out)
{
    extern __shared__ float sm[];
    float*  Wt  = sm + OFF_W;
    float4* hsd = (float4*)(sm + OFF_H);
    float*  red = sm + OFF_RED;
    float*  xs  = sm + OFF_X;

    const int tid   = threadIdx.x;
    const int lane  = tid & 31;
    const int wid   = tid >> 5;
    const int jhalf = wid & 1;         // which half of j-rows this warp covers
    const int kslot = wid >> 1;        // k residue (mod 8) this warp covers
    const int j0    = jhalf * 128 + lane * 4;
    const int b0    = blockIdx.x * 2;
    const int fb    = tid >> 8;        // finalize: batch
    const int fj    = tid & 255;       // finalize: j row

    // ---------------- init ----------------
    for (int i = tid; i < Tn; i += NT) {
        xs[i]      = x[(size_t)b0 * Tn + i];
        xs[Tn + i] = x[(size_t)(b0 + 1) * Tn + i];
    }
    // smem W: rows k in [KREG,256), transposed Wt[k-KREG][j]
    for (int idx = tid; idx < 256 * ((Hn - KREG) / 4); idx += NT) {
        int j  = idx / ((Hn - KREG) / 4);
        int kc = idx % ((Hn - KREG) / 4);
        int k0 = KREG + kc * 4;
        float4 w4 = *(const float4*)&W_hh[j * Hn + k0];
        Wt[(k0 - KREG + 0) * 256 + j] = w4.x;
        Wt[(k0 - KREG + 1) * 256 + j] = w4.y;
        Wt[(k0 - KREG + 2) * 256 + j] = w4.z;
        Wt[(k0 - KREG + 3) * 256 + j] = w4.w;
    }
    // register W: k = it*8 + kslot, packed as j-pairs for f32x2
    ull wr0[ITS_REG], wr1[ITS_REG];
    #pragma unroll
    for (int it = 0; it < ITS_REG; ++it) {
        int k = it * KSLOTS + kslot;
        wr0[it] = packf2(W_hh[(j0 + 0) * Hn + k], W_hh[(j0 + 1) * Hn + k]);
        wr1[it] = packf2(W_hh[(j0 + 2) * Hn + k], W_hh[(j0 + 3) * Hn + k]);
    }
    const float c1 = W_ih[fj];
    const float c0 = b_ih[fj] + b_hh[fj];
    if (tid < 256) hsd[tid] = make_float4(0.f, 0.f, 0.f, 0.f);
    __syncthreads();

    // ---------------- recurrence ----------------
    for (int t = 0; t < Tn; ++t) {
        ull a00 = 0, a01 = 0, a10 = 0, a11 = 0;  // a{jpair}{batch}

        // register-W part: k = it*8 + kslot
        const float4* hp = &hsd[kslot];
        #pragma unroll
        for (int it = 0; it < ITS_REG; ++it) {
            ulonglong2 hv = *(const ulonglong2*)(hp + it * KSLOTS);  // broadcast
            ffma2(a00, wr0[it], hv.x);
            ffma2(a01, wr0[it], hv.y);
            ffma2(a10, wr1[it], hv.x);
            ffma2(a11, wr1[it], hv.y);
        }
        // smem-W part: k = KREG + it*8 + kslot
        const float*  wp  = &Wt[kslot * 256 + j0];
        const float4* hp2 = &hsd[KREG + kslot];
        #pragma unroll
        for (int it = 0; it < ITS_SM; ++it) {
            ulonglong2 wv = *(const ulonglong2*)(wp + it * (KSLOTS * 256)); // contiguous
            ulonglong2 hv = *(const ulonglong2*)(hp2 + it * KSLOTS);        // broadcast
            ffma2(a00, wv.x, hv.x);
            ffma2(a01, wv.x, hv.y);
            ffma2(a10, wv.y, hv.x);
            ffma2(a11, wv.y, hv.y);
        }

        // k-slot partials
        {
            float2 p00 = u2f(a00), p10 = u2f(a10);
            float2 p01 = u2f(a01), p11 = u2f(a11);
            *(float4*)&red[(kslot * 2 + 0) * 256 + j0] = make_float4(p00.x, p00.y, p10.x, p10.y);
            *(float4*)&red[(kslot * 2 + 1) * 256 + j0] = make_float4(p01.x, p01.y, p11.x, p11.y);
        }
        __syncthreads();

        // finalize: thread (fb, fj) reduces its 8 k-slot partials
        {
            float s = red[fb * 256 + fj];
            #pragma unroll
            for (int r = 1; r < KSLOTS; ++r)
                s += red[(r * 2 + fb) * 256 + fj];
            float xv = xs[fb * Tn + t];
            float h  = tanh_fast(fmaf(xv, c1, c0) + s);
            *(float2*)(((float*)&hsd[fj]) + fb * 2) = make_float2(h, h);
        }
        __syncthreads();
    }

    // ---------------- output head ----------------
    if (tid < 2 * Pn) {
        int b = tid / Pn;
        int p = tid % Pn;
        float s = b_out[p];
        const float* wrow = &W_out[p * Hn];
        #pragma unroll 8
        for (int h = 0; h < Hn; ++h) {
            float4 hv = hsd[h];
            float hb = b ? hv.z : hv.x;
            s = fmaf(hb, wrow[h], s);
        }
        out[(size_t)(b0 + b) * Pn + p] = s;
    }
}

extern "C" void kernel_launch(void* const* d_in, const int* in_sizes, int n_in,
                              void* d_out, int out_size) {
    const float* x     = (const float*)d_in[0];
    const float* W_ih  = (const float*)d_in[1];
    const float* W_hh  = (const float*)d_in[2];
    const float* b_ih  = (const float*)d_in[3];
    const float* b_hh  = (const float*)d_in[4];
    const float* W_out = (const float*)d_in[5];
    const float* b_out = (const float*)d_in[6];
    float* out = (float*)d_out;

    cudaFuncSetAttribute(rnn_persistent_kernel,
                         cudaFuncAttributeMaxDynamicSharedMemorySize, SMEM_BYTES);
    rnn_persistent_kernel<<<Bn / 2, NT, SMEM_BYTES>>>(
        x, W_ih, W_hh, b_ih, b_hh, W_out, b_out, out);
}

// round 4
// speedup vs baseline: 1.4396x; 1.1624x over previous
#include <cuda_runtime.h>
#include <cstdint>

#define Tn 2048
#define Hn 256
#define Bn 256
#define Pn 24

#define NT      512       // 16 warps: 8 k-blocks x 2 j-halves
#define KSLOTS  8
#define KB_PER  32                       // k-rows per k-block (per kslot)
#define ITS_REG 20                       // first 20 k of each block in registers
#define ITS_SM  (KB_PER - ITS_REG)       // last 12 k of each block in smem
#define WSM_ROWS (KSLOTS * ITS_SM)       // 96 rows in smem

typedef unsigned long long ull;

// Shared memory layout (float offsets)
//  Wt  : [96][256] rows (kslot*12 + i) <-> k = kslot*32 + 20 + i   = 24576 floats (96 KB)
//  hb  : [2][256] batch-major hidden state                          =   512 floats ( 2 KB)
//  red : [16][256] (kslot*2 + b) partials                           =  4096 floats (16 KB)
//  xs  : [2][2048] cached x rows                                    =  4096 floats (16 KB)
#define OFF_W   0
#define OFF_H   24576
#define OFF_RED 25088
#define OFF_X   29184
#define SMEM_FLOATS 33280
#define SMEM_BYTES (SMEM_FLOATS * 4)

__device__ __forceinline__ void ffma2(ull& a, ull b, ull c) {
    asm("fma.rn.f32x2 %0, %1, %2, %0;" : "+l"(a) : "l"(b), "l"(c));
}
__device__ __forceinline__ ull packf2(float lo, float hi) {
    ull r; asm("mov.b64 %0, {%1, %2};" : "=l"(r) : "f"(lo), "f"(hi)); return r;
}
__device__ __forceinline__ ull dupf2(float v) {
    ull r; asm("mov.b64 %0, {%1, %1};" : "=l"(r) : "f"(v)); return r;
}
__device__ __forceinline__ float2 u2f(ull v) {
    float2 r; asm("mov.b64 {%0, %1}, %2;" : "=f"(r.x), "=f"(r.y) : "l"(v)); return r;
}
// tanh(x) = 1 - 2/(e^{2x}+1); ex2+rcp approx, abs err ~4e-7, saturates correctly.
__device__ __forceinline__ float tanh_fast(float v) {
    float e = __expf(2.0f * v);
    return 1.0f - __fdividef(2.0f, e + 1.0f);
}

__global__ void __launch_bounds__(NT, 1)
rnn_persistent_kernel(const float* __restrict__ x,
                      const float* __restrict__ W_ih,
                      const float* __restrict__ W_hh,
                      const float* __restrict__ b_ih,
                      const float* __restrict__ b_hh,
                      const float* __restrict__ W_out,
                      const float* __restrict__ b_out,
                      float* __restrict__ out)
{
    extern __shared__ float sm[];
    float* Wt  = sm + OFF_W;
    float* hb  = sm + OFF_H;
    float* red = sm + OFF_RED;
    float* xs  = sm + OFF_X;

    const int tid   = threadIdx.x;
    const int lane  = tid & 31;
    const int wid   = tid >> 5;
    const int jhalf = wid & 1;          // half of j-rows this warp covers
    const int kslot = wid >> 1;         // contiguous k-block [kslot*32, +32)
    const int kbase = kslot * KB_PER;
    const int j0    = jhalf * 128 + lane * 4;
    const int b0    = blockIdx.x * 2;
    const int fb    = tid >> 8;         // finalize: batch
    const int fj    = tid & 255;        // finalize: j row

    // ---------------- init ----------------
    for (int i = tid; i < Tn; i += NT) {
        xs[i]      = x[(size_t)b0 * Tn + i];
        xs[Tn + i] = x[(size_t)(b0 + 1) * Tn + i];
    }
    // smem W rows: row r -> k = (r/ITS_SM)*32 + ITS_REG + (r%ITS_SM), transposed over j
    for (int idx = tid; idx < 256 * (WSM_ROWS / 4); idx += NT) {
        int j  = idx / (WSM_ROWS / 4);
        int rc = idx % (WSM_ROWS / 4);
        // handle 4 consecutive smem rows per thread chunk
        #pragma unroll
        for (int q = 0; q < 4; ++q) {
            int r = rc * 4 + q;
            int k = (r / ITS_SM) * KB_PER + ITS_REG + (r % ITS_SM);
            Wt[r * 256 + j] = W_hh[j * Hn + k];
        }
    }
    // register W: k = kbase + i, i in [0,20), packed as j-pairs for f32x2
    ull wr0[ITS_REG], wr1[ITS_REG];
    #pragma unroll
    for (int i = 0; i < ITS_REG; ++i) {
        int k = kbase + i;
        wr0[i] = packf2(W_hh[(j0 + 0) * Hn + k], W_hh[(j0 + 1) * Hn + k]);
        wr1[i] = packf2(W_hh[(j0 + 2) * Hn + k], W_hh[(j0 + 3) * Hn + k]);
    }
    const float c1 = W_ih[fj];
    const float c0 = b_ih[fj] + b_hh[fj];
    if (tid < 512) hb[tid] = 0.f;
    __syncthreads();

    // ---------------- recurrence ----------------
    for (int t = 0; t < Tn; ++t) {
        ull a00 = 0, a01 = 0, a10 = 0, a11 = 0;  // a{jpair}{batch}

        const float4* h0p = (const float4*)(hb + kbase);        // batch 0
        const float4* h1p = (const float4*)(hb + 256 + kbase);  // batch 1

        // register-W part: blocks 0..4 (i = 0..19)
        #pragma unroll
        for (int blk = 0; blk < ITS_REG / 4; ++blk) {
            float4 hv0 = h0p[blk];   // broadcast LDS.128: h[k..k+3] batch0
            float4 hv1 = h1p[blk];   // broadcast LDS.128: h[k..k+3] batch1
            #pragma unroll
            for (int c = 0; c < 4; ++c) {
                int i = blk * 4 + c;
                ull d0 = dupf2(((const float*)&hv0)[c]);
                ull d1 = dupf2(((const float*)&hv1)[c]);
                ffma2(a00, wr0[i], d0);
                ffma2(a01, wr0[i], d1);
                ffma2(a10, wr1[i], d0);
                ffma2(a11, wr1[i], d1);
            }
        }
        // smem-W part: blocks 5..7 (i = 20..31), rows kslot*12 + (i-20)
        const float* wp = &Wt[(kslot * ITS_SM) * 256 + j0];
        #pragma unroll
        for (int blk = 0; blk < ITS_SM / 4; ++blk) {
            float4 hv0 = h0p[ITS_REG / 4 + blk];
            float4 hv1 = h1p[ITS_REG / 4 + blk];
            #pragma unroll
            for (int c = 0; c < 4; ++c) {
                int r = blk * 4 + c;
                ulonglong2 wv = *(const ulonglong2*)(wp + r * 256);  // contiguous LDS.128
                ull d0 = dupf2(((const float*)&hv0)[c]);
                ull d1 = dupf2(((const float*)&hv1)[c]);
                ffma2(a00, wv.x, d0);
                ffma2(a01, wv.x, d1);
                ffma2(a10, wv.y, d0);
                ffma2(a11, wv.y, d1);
            }
        }

        // k-slot partials
        {
            float2 p00 = u2f(a00), p10 = u2f(a10);
            float2 p01 = u2f(a01), p11 = u2f(a11);
            *(float4*)&red[(kslot * 2 + 0) * 256 + j0] = make_float4(p00.x, p00.y, p10.x, p10.y);
            *(float4*)&red[(kslot * 2 + 1) * 256 + j0] = make_float4(p01.x, p01.y, p11.x, p11.y);
        }
        __syncthreads();

        // finalize: thread (fb, fj) reduces its 8 k-block partials
        {
            float r0 = red[(0 * 2 + fb) * 256 + fj];
            float r1 = red[(1 * 2 + fb) * 256 + fj];
            float r2 = red[(2 * 2 + fb) * 256 + fj];
            float r3 = red[(3 * 2 + fb) * 256 + fj];
            float r4 = red[(4 * 2 + fb) * 256 + fj];
            float r5 = red[(5 * 2 + fb) * 256 + fj];
            float r6 = red[(6 * 2 + fb) * 256 + fj];
            float r7 = red[(7 * 2 + fb) * 256 + fj];
            float s  = ((r0 + r1) + (r2 + r3)) + ((r4 + r5) + (r6 + r7));
            float xv = xs[fb * Tn + t];
            float h  = tanh_fast(fmaf(xv, c1, c0) + s);
            hb[fb * 256 + fj] = h;   // contiguous store, 1 wavefront/warp
        }
        __syncthreads();
    }

    // ---------------- output head ----------------
    if (tid < 2 * Pn) {
        int b = tid / Pn;
        int p = tid % Pn;
        float s = b_out[p];
        const float* wrow = &W_out[p * Hn];
        const float* hrow = &hb[b * 256];
        #pragma unroll 8
        for (int h = 0; h < Hn; ++h)
            s = fmaf(hrow[h], wrow[h], s);
        out[(size_t)(b0 + b) * Pn + p] = s;
    }
}

extern "C" void kernel_launch(void* const* d_in, const int* in_sizes, int n_in,
                              void* d_out, int out_size) {
    const float* x     = (const float*)d_in[0];
    const float* W_ih  = (const float*)d_in[1];
    const float* W_hh  = (const float*)d_in[2];
    const float* b_ih  = (const float*)d_in[3];
    const float* b_hh  = (const float*)d_in[4];
    const float* W_out = (const float*)d_in[5];
    const float* b_out = (const float*)d_in[6];
    float* out = (float*)d_out;

    cudaFuncSetAttribute(rnn_persistent_kernel,
                         cudaFuncAttributeMaxDynamicSharedMemorySize, SMEM_BYTES);
    rnn_persistent_kernel<<<Bn / 2, NT, SMEM_BYTES>>>(
        x, W_ih, W_hh, b_ih, b_hh, W_out, b_out, out);
}